// round 2
// baseline (speedup 1.0000x reference)
#include <cuda_runtime.h>
#include <cstdint>

// HashGrid encode: 16 levels, F=2, T=2^19, base_res=16, per_level_scale=2.0,
// smoothstep, 2D. Levels 0..5 dense, 6..15 hashed.
//
// v2: (a) warp-coalesced stores via smem transpose (store wavefronts 256->32/warp)
//     (b) __ldcg (L2-only) for levels >=4 so levels 0..3 tables (170KB) stay L1-resident
//     (c) launch_bounds(256,4) -> ~64 regs for deeper load pipelining

#define NLEVELS 16
#define LOG2_T 19
#define TSIZE (1u << LOG2_T)
#define PRIME1 2654435761u

__global__ __launch_bounds__(256, 4) void hashgrid_encode_kernel(
    const float2* __restrict__ x,          // [N] points in [-1,1]
    const float2* __restrict__ table,      // [16 * T] float2 entries
    float* __restrict__ out,               // [N, 32]
    int n)
{
    // [warp][channel][point], padded to 33 for conflict-free scalar access
    __shared__ float ts[8][32][33];

    const int tid  = threadIdx.x;
    const int lane = tid & 31;
    const int warp = tid >> 5;
    const int i = blockIdx.x * 256 + tid;

    const bool active = (i < n);
    float x0 = 0.0f, x1 = 0.0f;
    if (active) {
        float2 xi = __ldg(&x[i]);
        x0 = xi.x * 0.5f + 0.5f;   // map [-1,1] -> [0,1]
        x1 = xi.y * 0.5f + 0.5f;
    }

#pragma unroll
    for (int l = 0; l < NLEVELS; ++l) {
        const unsigned res = 16u << l;                 // power of two
        const float scale = (float)(res - 1u);

        float p0 = x0 * scale + 0.5f;
        float p1 = x1 * scale + 0.5f;
        float fl0 = floorf(p0);
        float fl1 = floorf(p1);
        float fr0 = p0 - fl0;
        float fr1 = p1 - fl1;
        unsigned g0 = (unsigned)(int)fl0;
        unsigned g1 = (unsigned)(int)fl1;

        // smoothstep weights
        float w0 = fr0 * fr0 * (3.0f - 2.0f * fr0);
        float w1 = fr1 * fr1 * (3.0f - 2.0f * fr1);

        unsigned i00, i10, i01, i11;
        if (l <= 5) {
            const unsigned mask = (res * res) - 1u;
            unsigned b0 = g0 + g1 * res;
            unsigned b1 = g0 + (g1 + 1u) * res;
            i00 = b0 & mask;        i10 = (b0 + 1u) & mask;
            i01 = b1 & mask;        i11 = (b1 + 1u) & mask;
        } else {
            const unsigned hmask = TSIZE - 1u;
            unsigned hy0 = g1 * PRIME1;
            unsigned hy1 = (g1 + 1u) * PRIME1;
            i00 = (g0 ^ hy0) & hmask;        i10 = ((g0 + 1u) ^ hy0) & hmask;
            i01 = (g0 ^ hy1) & hmask;        i11 = ((g0 + 1u) ^ hy1) & hmask;
        }

        const float2* tl = table + (size_t)l * TSIZE;
        float2 f00, f10, f01, f11;
        if (l <= 3) {
            // small dense tables: let them live in L1
            f00 = __ldg(tl + i00);
            f10 = __ldg(tl + i10);
            f01 = __ldg(tl + i01);
            f11 = __ldg(tl + i11);
        } else {
            // big tables: L2-only, don't thrash L1
            f00 = __ldcg(tl + i00);
            f10 = __ldcg(tl + i10);
            f01 = __ldcg(tl + i01);
            f11 = __ldcg(tl + i11);
        }

        float c00 = (1.0f - w0) * (1.0f - w1);
        float c10 = w0 * (1.0f - w1);
        float c01 = (1.0f - w0) * w1;
        float c11 = w0 * w1;

        float sx = c00 * f00.x + c10 * f10.x + c01 * f01.x + c11 * f11.x;
        float sy = c00 * f00.y + c10 * f10.y + c01 * f01.y + c11 * f11.y;

        // bank = (channel + lane) % 32 -> conflict-free
        ts[warp][2 * l][lane]     = sx;
        ts[warp][2 * l + 1][lane] = sy;
    }
    __syncwarp();

    // Warp-coalesced output: warp owns points [wbase, wbase+32) = 4KB contiguous.
    // Each STG.128 covers 512 contiguous bytes (4 lines -> 4 wavefronts).
    const int wbase = blockIdx.x * 256 + warp * 32;
    if (wbase + 32 <= n) {
        float4* ob = reinterpret_cast<float4*>(out + (size_t)wbase * 32);
#pragma unroll
        for (int j = 0; j < 8; ++j) {
            int f = j * 128 + lane * 4;   // flat float index within warp tile
            int p = f >> 5;               // point within warp
            int c = f & 31;               // channel
            float4 v = make_float4(ts[warp][c + 0][p],
                                   ts[warp][c + 1][p],
                                   ts[warp][c + 2][p],
                                   ts[warp][c + 3][p]);
            ob[j * 32 + lane] = v;
        }
    } else if (active) {
        // tail fallback (not hit for N = 524288)
        float* ob = out + (size_t)i * 32;
#pragma unroll
        for (int c = 0; c < 32; ++c) ob[c] = ts[warp][c][lane];
    }
}

extern "C" void kernel_launch(void* const* d_in, const int* in_sizes, int n_in,
                              void* d_out, int out_size)
{
    const float2* x     = (const float2*)d_in[0];   // [N,2] float32
    const float2* table = (const float2*)d_in[1];   // [16, T, 2] float32
    float* out          = (float*)d_out;            // [N, 32] float32

    int n = in_sizes[0] / 2;
    int threads = 256;
    int blocks = (n + threads - 1) / threads;
    hashgrid_encode_kernel<<<blocks, threads>>>(x, table, out, n);
}